// round 12
// baseline (speedup 1.0000x reference)
#include <cuda_runtime.h>
#include <cstdint>

// Ragged (values, offsets[int32], dimension) -> dense [num_rows, 32] float32.
// One lane per output element; one warp == one 32-wide output row.
//   - value load:  lanes read values[st .. st+31] -> consecutive, 1-2 wavefronts
//   - store:       out[row*32 + col] -> exactly one 128B line per warp
//   - offsets:     uniform per warp -> broadcast loads, L1-resident
// No smem, no barriers, no vector loads -> minimal instructions, no alignment
// hazards, fully coalesced in both directions. Should be DRAM-bound.

__global__ __launch_bounds__(256)
void ragged_to_dense_32(const float* __restrict__ values,
                        const int* __restrict__ offsets,
                        float* __restrict__ out,
                        int num_rows, int total_vals) {
    int gid = blockIdx.x * blockDim.x + threadIdx.x;   // one output element
    int row = gid >> 5;                                // warp-uniform
    int col = gid & 31;                                // = lane id
    if (row >= num_rows) return;

    int st  = __ldg(&offsets[row]);                    // broadcast across warp
    int end = (row + 1 < num_rows) ? __ldg(&offsets[row + 1]) : total_vals;

    float v = 0.0f;
    if (col < end - st) v = __ldg(&values[st + col]);  // coalesced gather

    out[gid] = v;                                      // one 128B line per warp
}

// Generic fallback for dim != 32 (not expected for this problem's shapes).
__global__ void ragged_to_dense_generic(const float* __restrict__ values,
                                        const int* __restrict__ offsets,
                                        float* __restrict__ out,
                                        int num_rows, int dim,
                                        int total_vals) {
    long long gid = (long long)blockIdx.x * blockDim.x + threadIdx.x;
    long long n = (long long)num_rows * dim;
    if (gid >= n) return;
    int row = (int)(gid / dim);
    int col = (int)(gid - (long long)row * dim);
    int start = offsets[row];
    int end   = (row + 1 < num_rows) ? offsets[row + 1] : total_vals;
    int len = end - start;
    out[gid] = (col < len) ? values[start + col] : 0.0f;
}

extern "C" void kernel_launch(void* const* d_in, const int* in_sizes, int n_in,
                              void* d_out, int out_size) {
    const float* values  = (const float*)d_in[0];
    const int*   offsets = (const int*)d_in[1];
    int num_rows   = in_sizes[1];
    int total_vals = in_sizes[0];
    int dim        = out_size / num_rows;

    if (dim == 32) {
        long long n = (long long)num_rows * 32;        // 2^25 for this problem
        int block = 256;
        int grid = (int)((n + block - 1) / block);
        ragged_to_dense_32<<<grid, block>>>(values, offsets, (float*)d_out,
                                            num_rows, total_vals);
    } else {
        long long n = (long long)num_rows * dim;
        int block = 256;
        long long grid = (n + block - 1) / block;
        ragged_to_dense_generic<<<(int)grid, block>>>(values, offsets, (float*)d_out,
                                                      num_rows, dim, total_vals);
    }
}

// round 13
// speedup vs baseline: 3.6182x; 3.6182x over previous
#include <cuda_runtime.h>
#include <cstdint>

// Ragged (values, offsets[int32], dimension) -> dense [num_rows, 32] float32.
// One WARP processes 32 rows:
//   - lane l loads offsets[wrow0 + l]  -> ONE coalesced load covers 32 row starts
//   - unrolled r-loop: shfl-broadcast (st,end) of row r, lane=col loads
//     values[st_r + lane] predicated on col < len  -> consecutive addresses,
//     1-2 wavefronts, zero sector replay, 32 INDEPENDENT loads in flight (MLP)
//   - 32 coalesced stores, one 128B line each
// No smem, no barriers, scalar 32-bit accesses only.

__global__ __launch_bounds__(256)
void ragged_to_dense_32(const float* __restrict__ values,
                        const int* __restrict__ offsets,
                        float* __restrict__ out,
                        int num_rows, int total_vals) {
    const int warp_id = (blockIdx.x * blockDim.x + threadIdx.x) >> 5;
    const int lane    = threadIdx.x & 31;
    const int wrow0   = warp_id << 5;                 // first row of this warp
    if (wrow0 >= num_rows) return;

    // row starts for this warp's 32 rows (coalesced), plus the 33rd boundary
    int r_idx = wrow0 + lane;
    int off   = (r_idx < num_rows) ? __ldg(&offsets[r_idx]) : total_vals;
    int off32 = (wrow0 + 32 < num_rows) ? __ldg(&offsets[wrow0 + 32]) : total_vals;

    float v[32];
    #pragma unroll
    for (int r = 0; r < 32; r++) {
        int st = __shfl_sync(0xffffffffu, off, r);
        int en = (r < 31) ? __shfl_sync(0xffffffffu, off, r + 1) : off32;
        int len = en - st;
        v[r] = (lane < len) ? __ldg(&values[st + lane]) : 0.0f;
    }

    float* dst = out + (long long)wrow0 * 32 + lane;
    #pragma unroll
    for (int r = 0; r < 32; r++) {
        dst[r * 32] = v[r];                           // warp: one 128B line
    }
}

// Generic fallback for dim != 32 (not expected for this problem's shapes).
__global__ void ragged_to_dense_generic(const float* __restrict__ values,
                                        const int* __restrict__ offsets,
                                        float* __restrict__ out,
                                        int num_rows, int dim,
                                        int total_vals) {
    long long gid = (long long)blockIdx.x * blockDim.x + threadIdx.x;
    long long n = (long long)num_rows * dim;
    if (gid >= n) return;
    int row = (int)(gid / dim);
    int col = (int)(gid - (long long)row * dim);
    int start = offsets[row];
    int end   = (row + 1 < num_rows) ? offsets[row + 1] : total_vals;
    int len = end - start;
    out[gid] = (col < len) ? values[start + col] : 0.0f;
}

extern "C" void kernel_launch(void* const* d_in, const int* in_sizes, int n_in,
                              void* d_out, int out_size) {
    const float* values  = (const float*)d_in[0];
    const int*   offsets = (const int*)d_in[1];
    int num_rows   = in_sizes[1];
    int total_vals = in_sizes[0];
    int dim        = out_size / num_rows;

    if (dim == 32) {
        int warps = (num_rows + 31) / 32;             // 32768 warps
        int block = 256;                              // 8 warps per block
        int grid  = (warps * 32 + block - 1) / block; // 4096 blocks
        ragged_to_dense_32<<<grid, block>>>(values, offsets, (float*)d_out,
                                            num_rows, total_vals);
    } else {
        long long n = (long long)num_rows * dim;
        int block = 256;
        long long grid = (n + block - 1) / block;
        ragged_to_dense_generic<<<(int)grid, block>>>(values, offsets, (float*)d_out,
                                                      num_rows, dim, total_vals);
    }
}